// round 7
// baseline (speedup 1.0000x reference)
#include <cuda_runtime.h>

// AdaptivePooling2D: [16,225,225,256] f32 -> [16,7,7,256] f32 (channels_last)
// Windows [32*o, 32*o+33) both dims, weight 1/1089.
//
// Round-7: zero-redundancy reads. Thread = (b, c4, grp, seg).
//   seg<7: reads rows [32s, 32s+32) of its 8-column group EXACTLY ONCE.
//          Window s needs rows [32s, 32s+33): sum = S(seg=s) + firstrow(seg=s+1).
//          So scatter: 32-row sum -> window s; peeled first row (32s, the
//          boundary row) -> window s-1 (skip for s=0).
//   seg=7: reads row 224 only -> window 6.
// Every input element read once: 829.4 MB total (r4 re-read boundaries: 851).
// Keeps r4's rate-optimal shape: 8-col groups (4KB contiguous/warp/step),
// compile-time trip counts, unroll 2, ~37 regs. Peeling the first row keeps
// the boundary accumulator dead across the main loop (avoids r5's reg bloat).

#define BB 16
#define HH 225
#define WW 225
#define C4 64            // 256 channels / 4 (float4)
#define OX 7
#define OY 7
#define NGRP 29          // 28 groups of 8 cols (w 0..223) + 1 group {224}

__device__ __forceinline__ void scat(float* out, int b, int ox, int oy, int c4,
                                     float x, float y, float z, float w)
{
    float* o = out + ((((size_t)(b * OX + ox) * OY + oy) * C4 + c4) << 2);
    atomicAdd(o + 0, x);
    atomicAdd(o + 1, y);
    atomicAdd(o + 2, z);
    atomicAdd(o + 3, w);
}

__global__ void __launch_bounds__(256)
pool_norr_kernel(const float4* __restrict__ in, float* __restrict__ out)
{
    const int N = BB * C4 * NGRP * 8;      // 237,568 threads
    int idx = blockIdx.x * blockDim.x + threadIdx.x;
    if (idx >= N) return;

    const int c4 = idx & (C4 - 1);
    int t = idx >> 6;
    const int seg = t & 7;                 // row segment 0..7
    t >>= 3;
    const int grp = t % NGRP;
    const int b   = t / NGRP;

    const int w0 = grp * 8;
    const int h0 = seg * 32;               // seg==7 -> 224 (single row)

    // Column-window mapping (same as round 4).
    const int k    = grp >> 2;
    const int oyP  = (k < OY) ? k : (OY - 1);
    const bool dual = ((grp & 3) == 0) && (grp >= 4) && (grp <= 24);
    const int oyD  = k - 1;

    const float4* __restrict__ p =
        in + ((size_t)(b * HH + h0) * WW + w0) * C4 + c4;
    const size_t rs = (size_t)WW * C4;
    const float s = 1.0f / (33.0f * 33.0f);

    if (grp == NGRP - 1) {
        // ---- single column w=224 (feeds window 6 only; oyP==6, no dual) ----
        if (seg == 7) {
            float4 v = __ldg(p);
            scat(out, b, 6, oyP, c4, v.x * s, v.y * s, v.z * s, v.w * s);
        } else {
            // Peel first row (boundary) -> window seg-1.
            float4 v = __ldg(p);
            p += rs;
            if (seg > 0)
                scat(out, b, seg - 1, oyP, c4, v.x * s, v.y * s, v.z * s, v.w * s);
            float4 acc = v;
#pragma unroll 4
            for (int i = 0; i < 31; ++i) {
                v = __ldg(p);
                p += rs;
                acc.x += v.x; acc.y += v.y; acc.z += v.z; acc.w += v.w;
            }
            scat(out, b, seg, oyP, c4, acc.x * s, acc.y * s, acc.z * s, acc.w * s);
        }
        return;
    }

    // ---- 8-column group ----
    if (seg == 7) {
        // Row 224 only -> window 6.
        float4 v0 = __ldg(p + 0 * C4), v1 = __ldg(p + 1 * C4);
        float4 v2 = __ldg(p + 2 * C4), v3 = __ldg(p + 3 * C4);
        float4 v4 = __ldg(p + 4 * C4), v5 = __ldg(p + 5 * C4);
        float4 v6 = __ldg(p + 6 * C4), v7 = __ldg(p + 7 * C4);
        float gx = v0.x + v1.x + v2.x + v3.x + v4.x + v5.x + v6.x + v7.x;
        float gy = v0.y + v1.y + v2.y + v3.y + v4.y + v5.y + v6.y + v7.y;
        float gz = v0.z + v1.z + v2.z + v3.z + v4.z + v5.z + v6.z + v7.z;
        float gw = v0.w + v1.w + v2.w + v3.w + v4.w + v5.w + v6.w + v7.w;
        scat(out, b, 6, oyP, c4, gx * s, gy * s, gz * s, gw * s);
        if (dual)
            scat(out, b, 6, oyD, c4, v0.x * s, v0.y * s, v0.z * s, v0.w * s);
        return;
    }

    // Peel first row (row 32*seg = boundary row): scatter to window seg-1,
    // then fold into the accumulators for window seg.
    float4 acc, acc0;
    {
        float4 v0 = __ldg(p + 0 * C4), v1 = __ldg(p + 1 * C4);
        float4 v2 = __ldg(p + 2 * C4), v3 = __ldg(p + 3 * C4);
        float4 v4 = __ldg(p + 4 * C4), v5 = __ldg(p + 5 * C4);
        float4 v6 = __ldg(p + 6 * C4), v7 = __ldg(p + 7 * C4);
        p += rs;
        acc.x = v0.x + v1.x + v2.x + v3.x + v4.x + v5.x + v6.x + v7.x;
        acc.y = v0.y + v1.y + v2.y + v3.y + v4.y + v5.y + v6.y + v7.y;
        acc.z = v0.z + v1.z + v2.z + v3.z + v4.z + v5.z + v6.z + v7.z;
        acc.w = v0.w + v1.w + v2.w + v3.w + v4.w + v5.w + v6.w + v7.w;
        acc0 = v0;
        if (seg > 0) {
            scat(out, b, seg - 1, oyP, c4, acc.x * s, acc.y * s, acc.z * s, acc.w * s);
            if (dual)
                scat(out, b, seg - 1, oyD, c4, acc0.x * s, acc0.y * s, acc0.z * s, acc0.w * s);
        }
    }

    // Remaining 31 rows of this segment.
#pragma unroll 2
    for (int i = 0; i < 31; ++i) {
        float4 v0 = __ldg(p + 0 * C4), v1 = __ldg(p + 1 * C4);
        float4 v2 = __ldg(p + 2 * C4), v3 = __ldg(p + 3 * C4);
        float4 v4 = __ldg(p + 4 * C4), v5 = __ldg(p + 5 * C4);
        float4 v6 = __ldg(p + 6 * C4), v7 = __ldg(p + 7 * C4);
        p += rs;
        acc0.x += v0.x; acc0.y += v0.y; acc0.z += v0.z; acc0.w += v0.w;
        acc.x += v0.x + v1.x + v2.x + v3.x + v4.x + v5.x + v6.x + v7.x;
        acc.y += v0.y + v1.y + v2.y + v3.y + v4.y + v5.y + v6.y + v7.y;
        acc.z += v0.z + v1.z + v2.z + v3.z + v4.z + v5.z + v6.z + v7.z;
        acc.w += v0.w + v1.w + v2.w + v3.w + v4.w + v5.w + v6.w + v7.w;
    }

    // 32-row sum -> window seg.
    scat(out, b, seg, oyP, c4, acc.x * s, acc.y * s, acc.z * s, acc.w * s);
    if (dual)
        scat(out, b, seg, oyD, c4, acc0.x * s, acc0.y * s, acc0.z * s, acc0.w * s);
}

extern "C" void kernel_launch(void* const* d_in, const int* in_sizes, int n_in,
                              void* d_out, int out_size)
{
    (void)in_sizes; (void)n_in;
    const float4* in = (const float4*)d_in[0];
    float* out = (float*)d_out;

    // Output is poisoned (0xAA) by the harness; atomics need zeros.
    cudaMemsetAsync(d_out, 0, (size_t)out_size * sizeof(float));

    const int n = BB * C4 * NGRP * 8;      // 237,568
    pool_norr_kernel<<<(n + 255) / 256, 256>>>(in, out);
}